// round 7
// baseline (speedup 1.0000x reference)
#include <cuda_runtime.h>
#include <cstdint>

#define BATCH  64
#define TSTEPS 1024
#define DDIM   512
#define FDIM   512

#define CLUSTER 8
#define NB      4          // batches per cluster
#define FCHUNK  64         // features per CTA (512/8)
#define NCLUST  (BATCH / NB)       // 16
#define NCTA2   (NCLUST * CLUSTER) // 128

typedef unsigned long long ull;

// ---- packed fp32x2 helpers (Blackwell FFMA2, PTX-only) ----------------------
__device__ __forceinline__ ull fma2_(ull a, ull b, ull c) {
    ull d;
    asm("fma.rn.f32x2 %0, %1, %2, %3;" : "=l"(d) : "l"(a), "l"(b), "l"(c));
    return d;
}
__device__ __forceinline__ ull splat2_(float x) {
    ull d;
    unsigned u = __float_as_uint(x);
    asm("mov.b64 %0, {%1, %1};" : "=l"(d) : "r"(u));
    return d;
}
__device__ __forceinline__ float2 unpack2_(ull v) {
    unsigned lo, hi;
    asm("mov.b64 {%0, %1}, %2;" : "=r"(lo), "=r"(hi) : "l"(v));
    return make_float2(__uint_as_float(lo), __uint_as_float(hi));
}

// ----------------------------------------------------------------------------
// Phase 1: x_proj = inputs @ W_ih + bias   (M=65536, N=512, K=512, fp32)
// 128x128 CTA tile, 8x8 per-thread microtile as 8x4 f32x2 accumulators.
// ----------------------------------------------------------------------------
#define KT 16
__global__ __launch_bounds__(256, 2) void xproj_kernel(
    const float* __restrict__ A,     // [65536, 512]
    const float* __restrict__ W,     // [512, 512]
    const float* __restrict__ bias,  // [512]
    float* __restrict__ C)           // [65536, 512]
{
    __shared__ float As[KT][128];  // transposed A tile: As[k][m]
    __shared__ float Bs[KT][128];  // Bs[k][n]

    const int tid = threadIdx.x;
    const int m0 = blockIdx.y * 128;
    const int n0 = blockIdx.x * 128;
    const int tx = tid & 15;            // 16 threads in n
    const int ty = tid >> 4;            // 16 threads in m
    const int arow = tid >> 1;          // 0..127
    const int ak8  = (tid & 1) << 3;    // 0 or 8
    const int brow = tid >> 4;          // 0..15
    const int bc8  = (tid & 15) << 3;   // 0..120

    ull acc2[8][4];
#pragma unroll
    for (int i = 0; i < 8; i++)
#pragma unroll
        for (int p = 0; p < 4; p++) acc2[i][p] = 0ull;

    const float* Arow = A + (size_t)(m0 + arow) * DDIM + ak8;
    const float* Wrow = W + (size_t)brow * FDIM + n0 + bc8;

    for (int k0 = 0; k0 < DDIM; k0 += KT) {
        const float4 a0 = *(const float4*)(Arow + k0);
        const float4 a1 = *(const float4*)(Arow + k0 + 4);
        const float4 b0 = *(const float4*)(Wrow + (size_t)k0 * FDIM);
        const float4 b1 = *(const float4*)(Wrow + (size_t)k0 * FDIM + 4);
        __syncthreads();
        As[ak8 + 0][arow] = a0.x;
        As[ak8 + 1][arow] = a0.y;
        As[ak8 + 2][arow] = a0.z;
        As[ak8 + 3][arow] = a0.w;
        As[ak8 + 4][arow] = a1.x;
        As[ak8 + 5][arow] = a1.y;
        As[ak8 + 6][arow] = a1.z;
        As[ak8 + 7][arow] = a1.w;
        *(float4*)&Bs[brow][bc8]     = b0;
        *(float4*)&Bs[brow][bc8 + 4] = b1;
        __syncthreads();
#pragma unroll
        for (int k = 0; k < KT; k++) {
            float a[8];
            *(float4*)&a[0] = *(const float4*)&As[k][ty * 8];
            *(float4*)&a[4] = *(const float4*)&As[k][ty * 8 + 4];
            const ulonglong2 t0 = *(const ulonglong2*)&Bs[k][tx * 8];
            const ulonglong2 t1 = *(const ulonglong2*)&Bs[k][tx * 8 + 4];
            ull b2[4] = {t0.x, t0.y, t1.x, t1.y};
#pragma unroll
            for (int i = 0; i < 8; i++) {
                const ull a2 = splat2_(a[i]);
#pragma unroll
                for (int p = 0; p < 4; p++)
                    acc2[i][p] = fma2_(a2, b2[p], acc2[i][p]);
            }
        }
    }

    const int nb = n0 + tx * 8;
    float bv8[8];
#pragma unroll
    for (int j = 0; j < 8; j++) bv8[j] = bias[nb + j];

#pragma unroll
    for (int i = 0; i < 8; i++) {
        float* cp = C + (size_t)(m0 + ty * 8 + i) * FDIM + nb;
        const float2 c0 = unpack2_(acc2[i][0]);
        const float2 c1 = unpack2_(acc2[i][1]);
        const float2 c2 = unpack2_(acc2[i][2]);
        const float2 c3 = unpack2_(acc2[i][3]);
        *(float4*)cp = make_float4(c0.x + bv8[0], c0.y + bv8[1],
                                   c1.x + bv8[2], c1.y + bv8[3]);
        *(float4*)(cp + 4) = make_float4(c2.x + bv8[4], c2.y + bv8[5],
                                         c3.x + bv8[6], c3.y + bv8[7]);
    }
}

// ----------------------------------------------------------------------------
// Phase 2: sequential scan. Cluster of 8 CTAs per batch-group (4 batches).
// Each CTA: W_hh slice [512, 64] fp32 in SMEM; per step computes its F-chunk
// of h_next for the 4 batches (f32x2 FMAs), broadcasts via DSMEM, one cluster
// barrier per step.
// ----------------------------------------------------------------------------

// dynamic SMEM layout (floats):
//   Ws  [512*64]          = 32768   W_hh slice, Ws[k*64 + f]
//   H   [2][NB][512]      = 4096    double-buffered hidden state
//   RED [16][256]         = 4096    K-split partial sums
#define SM_WS   0
#define SM_H    (512 * FCHUNK)
#define SM_RED  (SM_H + 2 * NB * 512)
#define SM_FLOATS (SM_RED + 16 * 256)   // 40960 floats = 163840 B

__device__ __forceinline__ void cluster_sync_() {
    asm volatile("barrier.cluster.arrive.aligned;" ::: "memory");
    asm volatile("barrier.cluster.wait.aligned;" ::: "memory");
}

__device__ __forceinline__ float f4get(const float4 v, int j) {
    return j == 0 ? v.x : (j == 1 ? v.y : (j == 2 ? v.z : v.w));
}

extern __shared__ float smem2[];

__global__ __launch_bounds__(256, 1) __cluster_dims__(CLUSTER, 1, 1)
void rnn_scan_kernel(const float* __restrict__ w_hh,  // [512, 512]
                     float* __restrict__ xo)          // [B, T, F]: xp in, h out
{
    float* Ws  = smem2 + SM_WS;
    float* H   = smem2 + SM_H;
    float* RED = smem2 + SM_RED;

    const int tid  = threadIdx.x;
    const int rank = blockIdx.x % CLUSTER;   // cluster rank (x-major)
    const int bg   = blockIdx.x / CLUSTER;   // batch group 0..15
    const int f0   = rank * FCHUNK;

    // Load W_hh slice: Ws[k*64 + f] = w_hh[k*512 + f0 + f]
    for (int i = tid; i < 512 * FCHUNK; i += 256) {
        const int k = i >> 6;
        const int f = i & 63;
        Ws[i] = w_hh[k * FDIM + f0 + f];
    }
    // h(-1) = 0 lives in buffer 1 (step 0 reads buffer 1-p with p=0)
    for (int i = tid; i < NB * 512; i += 256) H[NB * 512 + i] = 0.f;
    __syncthreads();
    cluster_sync_();

    // compute-role indices
    const int f4    = tid & 15;   // feature quad 0..15
    const int ks    = tid >> 4;   // K slice 0..15
    const int kbase = ks * 32;
    // output-role indices
    const int ob = tid >> 6;      // 0..3
    const int of = tid & 63;      // 0..63
    const int bglob = bg * NB + ob;
    float* xo_ptr = xo + (size_t)bglob * TSTEPS * FDIM + f0 + of;

    // Precompute DSMEM remote addresses for both phase buffers, all 8 ranks.
    uint32_t raddr[2][CLUSTER];
    {
        uint32_t s;
        asm("{ .reg .u64 t; cvta.to.shared.u64 t, %1; cvt.u32.u64 %0, t; }"
            : "=r"(s) : "l"(smem2));
        const uint32_t h_u32 = s + (uint32_t)(SM_H * 4);
#pragma unroll
        for (int pp = 0; pp < 2; pp++) {
            const uint32_t laddr =
                h_u32 + (uint32_t)(((pp * NB + ob) * 512 + f0 + of) * 4);
#pragma unroll
            for (int r = 0; r < CLUSTER; r++) {
                asm("mapa.shared::cluster.u32 %0, %1, %2;"
                    : "=r"(raddr[pp][r]) : "r"(laddr), "r"(r));
            }
        }
    }

#pragma unroll 1
    for (int t = 0; t < TSTEPS; t++) {
        const int p = t & 1;
        const float xpv = xo_ptr[t * FDIM];        // issued early, hidden by K-loop
        const float* hp = H + (1 - p) * NB * 512;  // hp[b*512 + k]

        ull acc2[NB][2];
#pragma unroll
        for (int b = 0; b < NB; b++) { acc2[b][0] = 0ull; acc2[b][1] = 0ull; }

#pragma unroll
        for (int kk = 0; kk < 32; kk += 4) {
            const int k = kbase + kk;
            float4 hq[NB];
#pragma unroll
            for (int b = 0; b < NB; b++)
                hq[b] = *(const float4*)&hp[b * 512 + k];
#pragma unroll
            for (int j = 0; j < 4; j++) {
                const ulonglong2 w2 =
                    *(const ulonglong2*)&Ws[(k + j) * FCHUNK + (f4 << 2)];
#pragma unroll
                for (int b = 0; b < NB; b++) {
                    const ull h2 = splat2_(f4get(hq[b], j));
                    acc2[b][0] = fma2_(h2, w2.x, acc2[b][0]);
                    acc2[b][1] = fma2_(h2, w2.y, acc2[b][1]);
                }
            }
        }

        // write K-split partials: RED[ks][b*64 + f4*4 .. +3]
#pragma unroll
        for (int b = 0; b < NB; b++) {
            *(ulonglong2*)&RED[ks * 256 + b * 64 + (f4 << 2)] =
                make_ulonglong2(acc2[b][0], acc2[b][1]);
        }
        __syncthreads();

        // reduce 16 partials for output (ob, of) — 4-way split dependency tree
        float z0 = 0.f, z1 = 0.f, z2 = 0.f, z3 = 0.f;
#pragma unroll
        for (int s = 0; s < 16; s += 4) {
            z0 += RED[(s + 0) * 256 + tid];
            z1 += RED[(s + 1) * 256 + tid];
            z2 += RED[(s + 2) * 256 + tid];
            z3 += RED[(s + 3) * 256 + tid];
        }
        const float hv = tanhf(xpv + ((z0 + z1) + (z2 + z3)));

        // write output (overwrites the xp we just consumed)
        xo_ptr[t * FDIM] = hv;

        // broadcast h into every cluster CTA's H[p][ob][f0+of]
#pragma unroll
        for (int r = 0; r < CLUSTER; r++) {
            asm volatile("st.shared::cluster.f32 [%0], %1;"
                         :: "r"(raddr[p][r]), "f"(hv) : "memory");
        }
        cluster_sync_();   // release/acquire: h(p) visible cluster-wide
    }
}

// ----------------------------------------------------------------------------
extern "C" void kernel_launch(void* const* d_in, const int* in_sizes, int n_in,
                              void* d_out, int out_size)
{
    const float* inputs = (const float*)d_in[0];  // [64,1024,512]
    const float* w_ih   = (const float*)d_in[1];  // [512,512]
    const float* w_hh   = (const float*)d_in[2];  // [512,512]
    const float* bias   = (const float*)d_in[3];  // [512]
    float* out = (float*)d_out;                   // [64,1024,512]

    cudaFuncSetAttribute(rnn_scan_kernel,
                         cudaFuncAttributeMaxDynamicSharedMemorySize,
                         SM_FLOATS * 4);

    // Phase 1: x_proj into d_out
    {
        dim3 grid(FDIM / 128, (BATCH * TSTEPS) / 128);  // (4, 512)
        xproj_kernel<<<grid, 256>>>(inputs, w_ih, bias, out);
    }
    // Phase 2: sequential scan (clustered persistent kernel)
    {
        rnn_scan_kernel<<<NCTA2, 256, SM_FLOATS * 4>>>(w_hh, out);
    }
}

// round 8
// speedup vs baseline: 1.2094x; 1.2094x over previous
#include <cuda_runtime.h>
#include <cstdint>

#define BATCH  64
#define TSTEPS 1024
#define DDIM   512
#define FDIM   512

#define CLUSTER 8
#define NB      4          // batches per cluster
#define FCHUNK  64         // features per CTA (512/8)
#define NCLUST  (BATCH / NB)       // 16
#define NCTA2   (NCLUST * CLUSTER) // 128

// ----------------------------------------------------------------------------
// Phase 1: x_proj = inputs @ W_ih + bias   (M=65536, N=512, K=512, fp32)
// (round-5 version: known good)
// ----------------------------------------------------------------------------
__global__ __launch_bounds__(256) void xproj_kernel(
    const float* __restrict__ A,     // [65536, 512]
    const float* __restrict__ W,     // [512, 512]
    const float* __restrict__ bias,  // [512]
    float* __restrict__ C)           // [65536, 512]
{
    __shared__ float As[8][128];  // transposed A tile: As[k][m]
    __shared__ float Bs[8][128];  // Bs[k][n]

    const int tid = threadIdx.x;
    const int m0 = blockIdx.y * 128;
    const int n0 = blockIdx.x * 128;
    const int tx = tid & 15;     // 16 threads in n
    const int ty = tid >> 4;     // 16 threads in m
    const int arow = tid >> 1;          // 0..127
    const int ac4  = (tid & 1) << 2;    // 0 or 4
    const int brow = tid >> 5;          // 0..7
    const int bc4  = (tid & 31) << 2;   // 0..124

    float acc[8][8];
#pragma unroll
    for (int i = 0; i < 8; i++)
#pragma unroll
        for (int j = 0; j < 8; j++) acc[i][j] = 0.f;

    for (int k0 = 0; k0 < DDIM; k0 += 8) {
        const float4 av = *(const float4*)&A[(size_t)(m0 + arow) * DDIM + k0 + ac4];
        const float4 bv = *(const float4*)&W[(size_t)(k0 + brow) * FDIM + n0 + bc4];
        __syncthreads();
        As[ac4 + 0][arow] = av.x;
        As[ac4 + 1][arow] = av.y;
        As[ac4 + 2][arow] = av.z;
        As[ac4 + 3][arow] = av.w;
        *(float4*)&Bs[brow][bc4] = bv;
        __syncthreads();
#pragma unroll
        for (int k = 0; k < 8; k++) {
            float a[8], b[8];
            *(float4*)&a[0] = *(const float4*)&As[k][ty * 8];
            *(float4*)&a[4] = *(const float4*)&As[k][ty * 8 + 4];
            *(float4*)&b[0] = *(const float4*)&Bs[k][tx * 8];
            *(float4*)&b[4] = *(const float4*)&Bs[k][tx * 8 + 4];
#pragma unroll
            for (int i = 0; i < 8; i++)
#pragma unroll
                for (int j = 0; j < 8; j++)
                    acc[i][j] = fmaf(a[i], b[j], acc[i][j]);
        }
    }

    const int nb = n0 + tx * 8;
    float bv8[8];
#pragma unroll
    for (int j = 0; j < 8; j++) bv8[j] = bias[nb + j];

#pragma unroll
    for (int i = 0; i < 8; i++) {
        float* cp = C + (size_t)(m0 + ty * 8 + i) * FDIM + nb;
        float4 v0 = make_float4(acc[i][0] + bv8[0], acc[i][1] + bv8[1],
                                acc[i][2] + bv8[2], acc[i][3] + bv8[3]);
        float4 v1 = make_float4(acc[i][4] + bv8[4], acc[i][5] + bv8[5],
                                acc[i][6] + bv8[6], acc[i][7] + bv8[7]);
        *(float4*)cp = v0;
        *(float4*)(cp + 4) = v1;
    }
}

// ----------------------------------------------------------------------------
// Phase 2: sequential scan. Cluster of 8 CTAs per batch-group (4 batches).
// CHANGE vs round 5: each thread caches its 32x4 W_hh tile in 128 REGISTERS
// (loaded once from gmem). The per-step inner loop reads only h from SMEM.
// ----------------------------------------------------------------------------

// dynamic SMEM layout (floats):
//   H   [2][NB][512]      = 4096    double-buffered hidden state
//   RED [16][256]         = 4096    K-split partial sums
#define SM_H    0
#define SM_RED  (2 * NB * 512)
#define SM_FLOATS (SM_RED + 16 * 256)   // 8192 floats = 32768 B

__device__ __forceinline__ void cluster_sync_() {
    asm volatile("barrier.cluster.arrive.aligned;" ::: "memory");
    asm volatile("barrier.cluster.wait.aligned;" ::: "memory");
}

__device__ __forceinline__ float f4get(const float4 v, int j) {
    return j == 0 ? v.x : (j == 1 ? v.y : (j == 2 ? v.z : v.w));
}

extern __shared__ float smem2[];

__global__ __launch_bounds__(256, 1) __cluster_dims__(CLUSTER, 1, 1)
void rnn_scan_kernel(const float* __restrict__ w_hh,  // [512, 512]
                     float* __restrict__ xo)          // [B, T, F]: xp in, h out
{
    float* H   = smem2 + SM_H;
    float* RED = smem2 + SM_RED;

    const int tid  = threadIdx.x;
    const int rank = blockIdx.x % CLUSTER;   // cluster rank (x-major)
    const int bg   = blockIdx.x / CLUSTER;   // batch group 0..15
    const int f0   = rank * FCHUNK;

    // compute-role indices
    const int f4    = tid & 15;   // feature quad 0..15
    const int ks    = tid >> 4;   // K slice 0..15
    const int kbase = ks * 32;
    // output-role indices
    const int ob = tid >> 6;      // 0..3
    const int of = tid & 63;      // 0..63
    const int bglob = bg * NB + ob;
    float* xo_ptr = xo + (size_t)bglob * TSTEPS * FDIM + f0 + of;

    // Register-cached W tile: w4[kk] = w_hh[kbase+kk][f0 + f4*4 .. +3]
    float4 w4[32];
    {
        const float* wp = w_hh + (size_t)kbase * FDIM + f0 + (f4 << 2);
#pragma unroll
        for (int kk = 0; kk < 32; kk++)
            w4[kk] = *(const float4*)(wp + (size_t)kk * FDIM);
    }

    // h(-1) = 0 lives in buffer 1 (step 0 reads buffer 1-p with p=0)
    for (int i = tid; i < NB * 512; i += 256) H[NB * 512 + i] = 0.f;
    __syncthreads();
    cluster_sync_();

    // Precompute DSMEM remote addresses for both phase buffers, all 8 ranks.
    uint32_t raddr[2][CLUSTER];
    {
        uint32_t s;
        asm("{ .reg .u64 t; cvta.to.shared.u64 t, %1; cvt.u32.u64 %0, t; }"
            : "=r"(s) : "l"(smem2));
        const uint32_t h_u32 = s + (uint32_t)(SM_H * 4);
#pragma unroll
        for (int pp = 0; pp < 2; pp++) {
            const uint32_t laddr =
                h_u32 + (uint32_t)(((pp * NB + ob) * 512 + f0 + of) * 4);
#pragma unroll
            for (int r = 0; r < CLUSTER; r++) {
                asm("mapa.shared::cluster.u32 %0, %1, %2;"
                    : "=r"(raddr[pp][r]) : "r"(laddr), "r"(r));
            }
        }
    }

#pragma unroll 1
    for (int t = 0; t < TSTEPS; t++) {
        const int p = t & 1;
        const float xpv = xo_ptr[t * FDIM];        // issued early, hidden by K-loop
        const float* hp = H + (1 - p) * NB * 512;  // hp[b*512 + k]

        float acc[NB][4];
#pragma unroll
        for (int b = 0; b < NB; b++)
#pragma unroll
            for (int j = 0; j < 4; j++) acc[b][j] = 0.f;

#pragma unroll
        for (int kk = 0; kk < 32; kk += 4) {
            const int k = kbase + kk;
            float4 hq[NB];
#pragma unroll
            for (int b = 0; b < NB; b++)
                hq[b] = *(const float4*)&hp[b * 512 + k];
#pragma unroll
            for (int j = 0; j < 4; j++) {
                const float4 w = w4[kk + j];
#pragma unroll
                for (int b = 0; b < NB; b++) {
                    const float hb = f4get(hq[b], j);
                    acc[b][0] = fmaf(hb, w.x, acc[b][0]);
                    acc[b][1] = fmaf(hb, w.y, acc[b][1]);
                    acc[b][2] = fmaf(hb, w.z, acc[b][2]);
                    acc[b][3] = fmaf(hb, w.w, acc[b][3]);
                }
            }
        }

        // write K-split partials: RED[ks][b*64 + f4*4 .. +3]
#pragma unroll
        for (int b = 0; b < NB; b++) {
            *(float4*)&RED[ks * 256 + b * 64 + (f4 << 2)] =
                make_float4(acc[b][0], acc[b][1], acc[b][2], acc[b][3]);
        }
        __syncthreads();

        // reduce 16 partials for output (ob, of) — 4-way split dependency tree
        float z0 = 0.f, z1 = 0.f, z2 = 0.f, z3 = 0.f;
#pragma unroll
        for (int s = 0; s < 16; s += 4) {
            z0 += RED[(s + 0) * 256 + tid];
            z1 += RED[(s + 1) * 256 + tid];
            z2 += RED[(s + 2) * 256 + tid];
            z3 += RED[(s + 3) * 256 + tid];
        }
        const float hv = tanhf(xpv + ((z0 + z1) + (z2 + z3)));

        // write output (overwrites the xp we just consumed)
        xo_ptr[t * FDIM] = hv;

        // broadcast h into every cluster CTA's H[p][ob][f0+of]
#pragma unroll
        for (int r = 0; r < CLUSTER; r++) {
            asm volatile("st.shared::cluster.f32 [%0], %1;"
                         :: "r"(raddr[p][r]), "f"(hv) : "memory");
        }
        cluster_sync_();   // release/acquire: h(p) visible cluster-wide
    }
}

// ----------------------------------------------------------------------------
extern "C" void kernel_launch(void* const* d_in, const int* in_sizes, int n_in,
                              void* d_out, int out_size)
{
    const float* inputs = (const float*)d_in[0];  // [64,1024,512]
    const float* w_ih   = (const float*)d_in[1];  // [512,512]
    const float* w_hh   = (const float*)d_in[2];  // [512,512]
    const float* bias   = (const float*)d_in[3];  // [512]
    float* out = (float*)d_out;                   // [64,1024,512]

    cudaFuncSetAttribute(rnn_scan_kernel,
                         cudaFuncAttributeMaxDynamicSharedMemorySize,
                         SM_FLOATS * 4);

    // Phase 1: x_proj into d_out
    {
        dim3 grid(FDIM / 128, (BATCH * TSTEPS) / 128);  // (4, 512)
        xproj_kernel<<<grid, 256>>>(inputs, w_ih, bias, out);
    }
    // Phase 2: sequential scan (clustered persistent kernel)
    {
        rnn_scan_kernel<<<NCTA2, 256, SM_FLOATS * 4>>>(w_hh, out);
    }
}

// round 9
// speedup vs baseline: 1.5133x; 1.2513x over previous
#include <cuda_runtime.h>
#include <cstdint>

#define BATCH  64
#define TSTEPS 1024
#define DDIM   512
#define FDIM   512

#define CLUSTER 8
#define NB      4          // batches per cluster
#define FCHUNK  64         // features per CTA (512/8)
#define NCLUST  (BATCH / NB)       // 16
#define NCTA2   (NCLUST * CLUSTER) // 128

// ----------------------------------------------------------------------------
// Phase 1: x_proj = inputs @ W_ih + bias   (M=65536, N=512, K=512, fp32)
// (round-5/7 version: known good, untouched)
// ----------------------------------------------------------------------------
__global__ __launch_bounds__(256) void xproj_kernel(
    const float* __restrict__ A,     // [65536, 512]
    const float* __restrict__ W,     // [512, 512]
    const float* __restrict__ bias,  // [512]
    float* __restrict__ C)           // [65536, 512]
{
    __shared__ float As[8][128];  // transposed A tile: As[k][m]
    __shared__ float Bs[8][128];  // Bs[k][n]

    const int tid = threadIdx.x;
    const int m0 = blockIdx.y * 128;
    const int n0 = blockIdx.x * 128;
    const int tx = tid & 15;     // 16 threads in n
    const int ty = tid >> 4;     // 16 threads in m
    const int arow = tid >> 1;          // 0..127
    const int ac4  = (tid & 1) << 2;    // 0 or 4
    const int brow = tid >> 5;          // 0..7
    const int bc4  = (tid & 31) << 2;   // 0..124

    float acc[8][8];
#pragma unroll
    for (int i = 0; i < 8; i++)
#pragma unroll
        for (int j = 0; j < 8; j++) acc[i][j] = 0.f;

    for (int k0 = 0; k0 < DDIM; k0 += 8) {
        const float4 av = *(const float4*)&A[(size_t)(m0 + arow) * DDIM + k0 + ac4];
        const float4 bv = *(const float4*)&W[(size_t)(k0 + brow) * FDIM + n0 + bc4];
        __syncthreads();
        As[ac4 + 0][arow] = av.x;
        As[ac4 + 1][arow] = av.y;
        As[ac4 + 2][arow] = av.z;
        As[ac4 + 3][arow] = av.w;
        *(float4*)&Bs[brow][bc4] = bv;
        __syncthreads();
#pragma unroll
        for (int k = 0; k < 8; k++) {
            float a[8], b[8];
            *(float4*)&a[0] = *(const float4*)&As[k][ty * 8];
            *(float4*)&a[4] = *(const float4*)&As[k][ty * 8 + 4];
            *(float4*)&b[0] = *(const float4*)&Bs[k][tx * 8];
            *(float4*)&b[4] = *(const float4*)&Bs[k][tx * 8 + 4];
#pragma unroll
            for (int i = 0; i < 8; i++)
#pragma unroll
                for (int j = 0; j < 8; j++)
                    acc[i][j] = fmaf(a[i], b[j], acc[i][j]);
        }
    }

    const int nb = n0 + tx * 8;
    float bv8[8];
#pragma unroll
    for (int j = 0; j < 8; j++) bv8[j] = bias[nb + j];

#pragma unroll
    for (int i = 0; i < 8; i++) {
        float* cp = C + (size_t)(m0 + ty * 8 + i) * FDIM + nb;
        float4 v0 = make_float4(acc[i][0] + bv8[0], acc[i][1] + bv8[1],
                                acc[i][2] + bv8[2], acc[i][3] + bv8[3]);
        float4 v1 = make_float4(acc[i][4] + bv8[4], acc[i][5] + bv8[5],
                                acc[i][6] + bv8[6], acc[i][7] + bv8[7]);
        *(float4*)cp = v0;
        *(float4*)(cp + 4) = v1;
    }
}

// ----------------------------------------------------------------------------
// Phase 2: sequential scan. Cluster of 8 CTAs per batch-group (4 batches).
// W_hh slice lives in registers (round 7). NEW: per-step cluster barrier
// replaced by st.async + transaction-counted mbarrier handshake.
// ----------------------------------------------------------------------------

// dynamic SMEM byte layout:
//   H   [2][NB][512] f32   bytes [0, 16384)
//   RED [2][16][256] f32   bytes [16384, 49152)
//   mbar[2] u64            bytes [49152, 49168)
#define SMB_RED   16384
#define SMB_MBAR  49152
#define SMB_TOTAL 49184
#define H_STRIDE  (NB * 512)            // floats per H parity buffer
#define H_BYTES   (NB * 512 * 4)        // 8192 bytes per parity buffer
#define TX_BYTES  (CLUSTER * 256 * 4)   // 8192: incoming bytes per step

__device__ __forceinline__ void cluster_sync_() {
    asm volatile("barrier.cluster.arrive.aligned;" ::: "memory");
    asm volatile("barrier.cluster.wait.aligned;" ::: "memory");
}

__device__ __forceinline__ void mbar_init_(uint32_t mbar, uint32_t cnt) {
    asm volatile("mbarrier.init.shared.b64 [%0], %1;" :: "r"(mbar), "r"(cnt)
                 : "memory");
}

__device__ __forceinline__ void mbar_expect_tx_(uint32_t mbar, uint32_t bytes) {
    asm volatile("mbarrier.arrive.expect_tx.shared.b64 _, [%0], %1;"
                 :: "r"(mbar), "r"(bytes) : "memory");
}

__device__ __forceinline__ void wait_parity_(uint32_t mbar, uint32_t phase) {
    asm volatile(
        "{\n\t"
        ".reg .pred P;\n\t"
        "WL%=:\n\t"
        "mbarrier.try_wait.parity.acquire.cluster.shared::cta.b64 P, [%0], %1, 0x989680;\n\t"
        "@P bra.uni WD%=;\n\t"
        "bra.uni WL%=;\n\t"
        "WD%=:\n\t"
        "}"
        :: "r"(mbar), "r"(phase) : "memory");
}

__device__ __forceinline__ void st_async_f32_(uint32_t raddr, float v,
                                              uint32_t rmbar) {
    asm volatile(
        "st.async.shared::cluster.mbarrier::complete_tx::bytes.b32 [%0], %1, [%2];"
        :: "r"(raddr), "r"(__float_as_uint(v)), "r"(rmbar) : "memory");
}

__device__ __forceinline__ float f4get(const float4 v, int j) {
    return j == 0 ? v.x : (j == 1 ? v.y : (j == 2 ? v.z : v.w));
}

extern __shared__ float smem2[];

__global__ __launch_bounds__(256, 1) __cluster_dims__(CLUSTER, 1, 1)
void rnn_scan_kernel(const float* __restrict__ w_hh,  // [512, 512]
                     float* __restrict__ xo)          // [B, T, F]: xp in, h out
{
    float* H   = smem2;                 // [2][NB][512]
    float* RED = smem2 + SMB_RED / 4;   // [2][16][256]

    const int tid  = threadIdx.x;
    const int rank = blockIdx.x % CLUSTER;   // cluster rank (x-major)
    const int bg   = blockIdx.x / CLUSTER;   // batch group 0..15
    const int f0   = rank * FCHUNK;

    // compute-role indices
    const int f4    = tid & 15;   // feature quad 0..15
    const int ks    = tid >> 4;   // K slice 0..15
    const int kbase = ks * 32;
    // output-role indices
    const int ob = tid >> 6;      // 0..3
    const int of = tid & 63;      // 0..63
    float* xo_ptr = xo + (size_t)(bg * NB + ob) * TSTEPS * FDIM + f0 + of;

    // Register-cached W tile: w4[kk] = w_hh[kbase+kk][f0 + f4*4 .. +3]
    float4 w4[32];
    {
        const float* wp = w_hh + (size_t)kbase * FDIM + f0 + (f4 << 2);
#pragma unroll
        for (int kk = 0; kk < 32; kk++)
            w4[kk] = *(const float4*)(wp + (size_t)kk * FDIM);
    }

    // SMEM base as u32
    uint32_t sbase;
    asm("{ .reg .u64 t; cvta.to.shared.u64 t, %1; cvt.u32.u64 %0, t; }"
        : "=r"(sbase) : "l"(smem2));
    const uint32_t mbar0 = sbase + SMB_MBAR;   // mbar[p] = mbar0 + p*8

    if (tid == 0) {
        mbar_init_(mbar0, 1);
        mbar_init_(mbar0 + 8, 1);
    }
    // h(-1) = 0 in buffer 1 (step 0 reads buffer 1)
    for (int i = tid; i < H_STRIDE; i += 256) H[H_STRIDE + i] = 0.f;
    __syncthreads();
    if (tid == 0) mbar_expect_tx_(mbar0, TX_BYTES);  // phase 0 of mbar[0] (step 0 stores)
    cluster_sync_();  // peers' mbar init + expect + H zeros visible before any st.async

    // Remote H-slot base addresses (p=0) for all ranks; other targets derived
    // by constant offsets (mapa is offset-linear within a target CTA).
    const uint32_t h0_byte = (uint32_t)((ob * 512 + f0 + of) * 4);
    uint32_t ra0[CLUSTER];
#pragma unroll
    for (int r = 0; r < CLUSTER; r++) {
        asm("mapa.shared::cluster.u32 %0, %1, %2;"
            : "=r"(ra0[r]) : "r"(sbase + h0_byte), "r"(r));
    }
    const uint32_t d_mb = (uint32_t)SMB_MBAR - h0_byte;  // slot -> mbar[0] delta

#pragma unroll 1
    for (int t = 0; t < TSTEPS; t++) {
        const int p = t & 1;
        const float xpv = xo_ptr[t * FDIM];   // LDG issued before the wait

        // wait for h(t-1) = buffer (1-p), written at step t-1
        if (t > 0)
            wait_parity_(mbar0 + (1 - p) * 8, ((uint32_t)(t - 1) >> 1) & 1);
        // post expectation for step t+1's stores (buffer 1-p). Safe: peers
        // cannot issue step-(t+1) stores until they received OUR step-t
        // stores, which this thread issues later in program order.
        if (tid == 0 && t < TSTEPS - 2)
            mbar_expect_tx_(mbar0 + (1 - p) * 8, TX_BYTES);

        const float* hp = H + (1 - p) * H_STRIDE;  // hp[b*512 + k]

        float acc[NB][4];
#pragma unroll
        for (int b = 0; b < NB; b++)
#pragma unroll
            for (int j = 0; j < 4; j++) acc[b][j] = 0.f;

#pragma unroll
        for (int kk = 0; kk < 32; kk += 4) {
            const int k = kbase + kk;
            float4 hq[NB];
#pragma unroll
            for (int b = 0; b < NB; b++)
                hq[b] = *(const float4*)&hp[b * 512 + k];
#pragma unroll
            for (int j = 0; j < 4; j++) {
                const float4 w = w4[kk + j];
#pragma unroll
                for (int b = 0; b < NB; b++) {
                    const float hb = f4get(hq[b], j);
                    acc[b][0] = fmaf(hb, w.x, acc[b][0]);
                    acc[b][1] = fmaf(hb, w.y, acc[b][1]);
                    acc[b][2] = fmaf(hb, w.z, acc[b][2]);
                    acc[b][3] = fmaf(hb, w.w, acc[b][3]);
                }
            }
        }

        // write K-split partials into parity-indexed RED buffer
        float* REDp = RED + p * (16 * 256);
#pragma unroll
        for (int b = 0; b < NB; b++) {
            *(float4*)&REDp[ks * 256 + b * 64 + (f4 << 2)] =
                make_float4(acc[b][0], acc[b][1], acc[b][2], acc[b][3]);
        }
        __syncthreads();   // the ONLY intra-CTA barrier per step

        // reduce 16 partials for output (ob, of) — 4-way split dependency tree
        float z0 = 0.f, z1 = 0.f, z2 = 0.f, z3 = 0.f;
#pragma unroll
        for (int s = 0; s < 16; s += 4) {
            z0 += REDp[(s + 0) * 256 + tid];
            z1 += REDp[(s + 1) * 256 + tid];
            z2 += REDp[(s + 2) * 256 + tid];
            z3 += REDp[(s + 3) * 256 + tid];
        }
        const float hv = tanhf(xpv + ((z0 + z1) + (z2 + z3)));

        // write output (overwrites the xp we just consumed)
        xo_ptr[t * FDIM] = hv;

        // broadcast h(t) into every cluster CTA's H[p][ob][f0+of] with
        // transaction-counted async stores (no cluster barrier).
        if (t < TSTEPS - 1) {
            const uint32_t rb = (uint32_t)(p * H_BYTES);
            const uint32_t db = d_mb + (uint32_t)(p * 8);
#pragma unroll
            for (int r = 0; r < CLUSTER; r++)
                st_async_f32_(ra0[r] + rb, hv, ra0[r] + db);
        }
    }
    // No trailing sync needed: step-1022 stores were consumed by the step-1023
    // waits (all delivered); step 1023 issues no DSMEM traffic.
}

// ----------------------------------------------------------------------------
extern "C" void kernel_launch(void* const* d_in, const int* in_sizes, int n_in,
                              void* d_out, int out_size)
{
    const float* inputs = (const float*)d_in[0];  // [64,1024,512]
    const float* w_ih   = (const float*)d_in[1];  // [512,512]
    const float* w_hh   = (const float*)d_in[2];  // [512,512]
    const float* bias   = (const float*)d_in[3];  // [512]
    float* out = (float*)d_out;                   // [64,1024,512]

    cudaFuncSetAttribute(rnn_scan_kernel,
                         cudaFuncAttributeMaxDynamicSharedMemorySize,
                         SMB_TOTAL);

    // Phase 1: x_proj into d_out
    {
        dim3 grid(FDIM / 128, (BATCH * TSTEPS) / 128);  // (4, 512)
        xproj_kernel<<<grid, 256>>>(inputs, w_ih, bias, out);
    }
    // Phase 2: sequential scan (clustered persistent kernel)
    {
        rnn_scan_kernel<<<NCTA2, 256, SMB_TOTAL>>>(w_hh, out);
    }
}